// round 11
// baseline (speedup 1.0000x reference)
#include <cuda_runtime.h>
#include <cuda_bf16.h>
#include <cstdint>
#include <stdint.h>

// ---------------------------------------------------------------------------
// 3-layer GCN:  relu(gcn(x,Wr)) -> relu(gcn(.,W2)) -> gcn(.,W1)
// gcn(x,W): out[v] = dis[v]*( sum_{s->v} h_s[s] + h_s[v] ) + b
//           where h_s = (x@W) * dis[row],  dis = rsqrt(indeg+1)
// GEMM: tensor cores, bf16 hi/lo split (3x mma). A and B pre-split in gmem.
// Whole A-tile + whole B resident in smem: ONE sync, no mainloop pipeline.
// ---------------------------------------------------------------------------

#define N_MAX 50000
#define E_MAX 640000
#define D     128
#define NCH_MAX 64

// scratch (static device memory: allocation-free rule)
__device__ float g_h[N_MAX * D];                       // h_scaled (gemm out)
__device__ float g_dis_role[N_MAX];
__device__ float g_dis_norm[N_MAX];
__device__ int   g_cnt_role[N_MAX];
__device__ int   g_cnt_norm[N_MAX];
__device__ int   g_fill_role[N_MAX];
__device__ int   g_fill_norm[N_MAX];
__device__ int   g_loc_role[N_MAX];
__device__ int   g_loc_norm[N_MAX];
__device__ int   g_tot[2 * NCH_MAX];
__device__ int   g_off[2 * NCH_MAX];
__device__ int   g_col_role[E_MAX];
__device__ int   g_col_norm[E_MAX];
// pre-split operands (bf16 hi/lo)
__device__ __align__(16) __nv_bfloat16 g_xh[N_MAX * D];   // split of input x
__device__ __align__(16) __nv_bfloat16 g_xl[N_MAX * D];
__device__ __align__(16) __nv_bfloat16 g_ah[N_MAX * D];   // split activations
__device__ __align__(16) __nv_bfloat16 g_al[N_MAX * D];
// split+transposed weights: [w][n][k] bf16 hi / lo
__device__ __align__(16) __nv_bfloat16 g_WTh[3 * D * D];
__device__ __align__(16) __nv_bfloat16 g_WTl[3 * D * D];

// ---------------------------------------------------------------------------
__device__ __forceinline__ void split4(float4 v, uint2& hv, uint2& lv) {
    __nv_bfloat16 hx = __float2bfloat16(v.x);
    __nv_bfloat16 hy = __float2bfloat16(v.y);
    __nv_bfloat16 hz = __float2bfloat16(v.z);
    __nv_bfloat16 hw = __float2bfloat16(v.w);
    __nv_bfloat16 lx = __float2bfloat16(v.x - __bfloat162float(hx));
    __nv_bfloat16 ly = __float2bfloat16(v.y - __bfloat162float(hy));
    __nv_bfloat16 lz = __float2bfloat16(v.z - __bfloat162float(hz));
    __nv_bfloat16 lw = __float2bfloat16(v.w - __bfloat162float(hw));
    hv.x = (uint32_t)__bfloat16_as_ushort(hx) |
           ((uint32_t)__bfloat16_as_ushort(hy) << 16);
    hv.y = (uint32_t)__bfloat16_as_ushort(hz) |
           ((uint32_t)__bfloat16_as_ushort(hw) << 16);
    lv.x = (uint32_t)__bfloat16_as_ushort(lx) |
           ((uint32_t)__bfloat16_as_ushort(ly) << 16);
    lv.y = (uint32_t)__bfloat16_as_ushort(lz) |
           ((uint32_t)__bfloat16_as_ushort(lw) << 16);
}

// prep: zero counters AND split/transpose the 3 weight matrices
__global__ void prep_kernel(const float* __restrict__ Wr,
                            const float* __restrict__ W2,
                            const float* __restrict__ W1, int n) {
    int i = blockIdx.x * blockDim.x + threadIdx.x;
    if (i < n) {
        g_cnt_role[i]  = 0;
        g_cnt_norm[i]  = 0;
        g_fill_role[i] = 0;
        g_fill_norm[i] = 0;
    }
    if (i < 3 * D * D) {
        int w = i >> 14, rem = i & 16383;
        int k = rem >> 7, nn = rem & 127;
        const float* W = (w == 0) ? Wr : (w == 1) ? W2 : W1;
        float v = W[k * D + nn];
        __nv_bfloat16 h = __float2bfloat16(v);
        __nv_bfloat16 l = __float2bfloat16(v - __bfloat162float(h));
        g_WTh[w * D * D + nn * D + k] = h;   // [n][k] layout (col-major B)
        g_WTl[w * D * D + nn * D + k] = l;
    }
}

// counts for both graphs + split x into bf16 hi/lo
__global__ void count_split_kernel(const int* __restrict__ dst_n,
                                   const int* __restrict__ dst_r, int E,
                                   const float4* __restrict__ X4, int NS4) {
    int i = blockIdx.x * blockDim.x + threadIdx.x;
    if (i < E) {
        atomicAdd(&g_cnt_norm[dst_n[i]], 1);
        atomicAdd(&g_cnt_role[dst_r[i]], 1);
    }
    if (i < NS4) {
        uint2 hv, lv;
        split4(X4[i], hv, lv);
        ((uint2*)g_xh)[i] = hv;
        ((uint2*)g_xl)[i] = lv;
    }
}

__global__ __launch_bounds__(1024) void scan_local_kernel(int n) {
    const int g = blockIdx.y;
    const int* __restrict__ cnt = g ? g_cnt_role : g_cnt_norm;
    int* __restrict__ loc       = g ? g_loc_role : g_loc_norm;
    float* __restrict__ dis     = g ? g_dis_role : g_dis_norm;

    __shared__ int wsum[32];
    int tid  = threadIdx.x;
    int lane = tid & 31, wid = tid >> 5;
    int i = (blockIdx.x << 10) + tid;
    int v = (i < n) ? cnt[i] : 0;

    int s = v;
    #pragma unroll
    for (int o = 1; o < 32; o <<= 1) {
        int t = __shfl_up_sync(0xffffffffu, s, o);
        if (lane >= o) s += t;
    }
    if (lane == 31) wsum[wid] = s;
    __syncthreads();
    if (wid == 0) {
        int w = wsum[lane];
        #pragma unroll
        for (int o = 1; o < 32; o <<= 1) {
            int t = __shfl_up_sync(0xffffffffu, w, o);
            if (lane >= o) w += t;
        }
        wsum[lane] = w;
    }
    __syncthreads();
    int woff = (wid == 0) ? 0 : wsum[wid - 1];
    int ex = s - v + woff;
    if (i < n) {
        loc[i] = ex;
        dis[i] = rsqrtf((float)(v + 1));
    }
    if (tid == 0) g_tot[g * NCH_MAX + blockIdx.x] = wsum[31];
}

__global__ void scan_mid_kernel(int nch) {
    int g = threadIdx.x >> 5, lane = threadIdx.x & 31;
    int carry = 0;
    for (int c0 = 0; c0 < nch; c0 += 32) {
        int idx = c0 + lane;
        int v = (idx < nch) ? g_tot[g * NCH_MAX + idx] : 0;
        int s = v;
        #pragma unroll
        for (int o = 1; o < 32; o <<= 1) {
            int t = __shfl_up_sync(0xffffffffu, s, o);
            if (lane >= o) s += t;
        }
        if (idx < nch) g_off[g * NCH_MAX + idx] = carry + s - v;
        carry += __shfl_sync(0xffffffffu, s, 31);
    }
}

__global__ void scatter_kernel(const int* __restrict__ src_n,
                               const int* __restrict__ dst_n,
                               const int* __restrict__ src_r,
                               const int* __restrict__ dst_r, int E) {
    const int g = blockIdx.y;
    const int* __restrict__ src = g ? src_r : src_n;
    const int* __restrict__ dst = g ? dst_r : dst_n;
    const int* __restrict__ loc = g ? g_loc_role : g_loc_norm;
    int* __restrict__ fill      = g ? g_fill_role : g_fill_norm;
    int* __restrict__ col       = g ? g_col_role : g_col_norm;
    const int* off = &g_off[g * NCH_MAX];

    int e = blockIdx.x * blockDim.x + threadIdx.x;
    if (e < E) {
        int d = dst[e];
        int pos = loc[d] + off[d >> 10] + atomicAdd(&fill[d], 1);
        col[pos] = src[e];
    }
}

// ---------------------------------------------------------------------------
// Tensor-core GEMM: H = (A @ W) * dis[row], A/B pre-split bf16 hi/lo in gmem.
// BM=64, BN=128, FULL K resident: one cp.async burst, ONE sync, then
// 8 unrolled k-steps of pure ldmatrix+mma. 256 threads = 8 warps (2x4).
// acc += Ah*Bh + Ah*Bl + Al*Bh.
// smem rows padded to 272 B (272 mod 128 = 16 -> LDSM conflict-free).
// ---------------------------------------------------------------------------
#define AROW 272u
#define A_HALF  17408u                 // 64 * 272
#define B_HALF  34816u                 // 128 * 272
#define SM_AH   0u
#define SM_AL   17408u
#define SM_BH   34816u
#define SM_BL   69632u
#define SMEM_TOTAL_GEMM 104448u        // 102 KB -> 2 CTAs/SM

#define MMA16816(d, a, b0, b1)                                                \
    asm volatile(                                                             \
        "mma.sync.aligned.m16n8k16.row.col.f32.bf16.bf16.f32 "                \
        "{%0,%1,%2,%3}, {%4,%5,%6,%7}, {%8,%9}, {%0,%1,%2,%3};"               \
        : "+f"((d)[0]), "+f"((d)[1]), "+f"((d)[2]), "+f"((d)[3])              \
        : "r"((a)[0]), "r"((a)[1]), "r"((a)[2]), "r"((a)[3]),                 \
          "r"(b0), "r"(b1))

#define LDSM4(r, addr)                                                        \
    asm volatile(                                                             \
        "ldmatrix.sync.aligned.m8n8.x4.shared.b16 {%0,%1,%2,%3}, [%4];"       \
        : "=r"((r)[0]), "=r"((r)[1]), "=r"((r)[2]), "=r"((r)[3])              \
        : "r"(addr))

__device__ __forceinline__ void cp16(uint32_t dst, const void* src) {
    asm volatile("cp.async.cg.shared.global [%0], [%1], 16;"
                 :: "r"(dst), "l"(src));
}
__device__ __forceinline__ void cp16p(uint32_t dst, const void* src,
                                      uint32_t sz) {
    asm volatile("cp.async.cg.shared.global [%0], [%1], 16, %2;"
                 :: "r"(dst), "l"(src), "r"(sz));
}

__global__ __launch_bounds__(256, 2) void gemm_tc_kernel(
    const __nv_bfloat16* __restrict__ Ah_g,
    const __nv_bfloat16* __restrict__ Al_g,
    const __nv_bfloat16* __restrict__ WTh,
    const __nv_bfloat16* __restrict__ WTl,
    const float* __restrict__ dis, float* __restrict__ H, int M)
{
    extern __shared__ char sm[];
    const uint32_t sb = (uint32_t)__cvta_generic_to_shared(sm);

    const int t    = threadIdx.x;
    const int lane = t & 31, wid = t >> 5;
    const int wm = wid >> 2;          // 0..1 : rows wm*32
    const int wn = wid & 3;           // 0..3 : cols wn*32
    const int gp = lane >> 2;
    const int tg = lane & 3;
    const int row0 = blockIdx.x * 64;

    // ldmatrix lane address components
    const int laneRowA = (lane & 7) + ((lane >> 3) & 1) * 8;
    const int laneKA   = (lane >> 4) * 16;                 // bytes
    const int laneRowB = (lane & 7) + ((lane >> 4) & 1) * 8;
    const int laneKB   = ((lane >> 3) & 1) * 16;           // bytes

    // ---- one-shot loads: A tile (64 x 128, hi+lo), full B (128 x 128, hi+lo)
    {
        const int ar = t >> 2, ac = t & 3;     // A row, 16B chunk
        const uint32_t aOK = (row0 + ar < M) ? 16u : 0u;
        #pragma unroll
        for (int p = 0; p < 4; p++) {
            uint32_t doff = (uint32_t)ar * AROW + (uint32_t)(ac * 16 + p * 64);
            size_t   soff = (size_t)(row0 + ar) * 128 + ac * 8 + p * 32;
            cp16p(sb + SM_AH + doff, Ah_g + soff, aOK);
            cp16p(sb + SM_AL + doff, Al_g + soff, aOK);
        }
        const int br = t >> 1, bc = t & 1;     // B row, 16B chunk
        #pragma unroll
        for (int p = 0; p < 8; p++) {
            uint32_t doff = (uint32_t)br * AROW + (uint32_t)(bc * 16 + p * 32);
            size_t   soff = (size_t)br * 128 + bc * 8 + p * 16;
            cp16(sb + SM_BH + doff, WTh + soff);
            cp16(sb + SM_BL + doff, WTl + soff);
        }
        asm volatile("cp.async.commit_group;");
        asm volatile("cp.async.wait_group 0;");
    }
    __syncthreads();

    float acc[2][4][4];
    #pragma unroll
    for (int mi = 0; mi < 2; mi++)
        #pragma unroll
        for (int ni = 0; ni < 4; ni++)
            #pragma unroll
            for (int j = 0; j < 4; j++) acc[mi][ni][j] = 0.f;

    const uint32_t aHb = sb + SM_AH, aLb = sb + SM_AL;
    const uint32_t bHb = sb + SM_BH, bLb = sb + SM_BL;

    #pragma unroll
    for (int kk = 0; kk < 128; kk += 16) {
        uint32_t bh[2][4], bl[2][4];
        #pragma unroll
        for (int pair = 0; pair < 2; pair++) {
            uint32_t off = (uint32_t)(wn * 32 + pair * 16 + laneRowB) * AROW
                           + (uint32_t)(kk * 2 + laneKB);
            LDSM4(bh[pair], bHb + off);
            LDSM4(bl[pair], bLb + off);
        }
        #pragma unroll
        for (int mi = 0; mi < 2; mi++) {
            uint32_t ah[4], al[4];
            uint32_t off = (uint32_t)(wm * 32 + mi * 16 + laneRowA) * AROW
                           + (uint32_t)(kk * 2 + laneKA);
            LDSM4(ah, aHb + off);
            LDSM4(al, aLb + off);
            #pragma unroll
            for (int ni = 0; ni < 4; ni++) {
                int pair = ni >> 1, sbi = (ni & 1) * 2;
                MMA16816(acc[mi][ni], ah, bh[pair][sbi], bh[pair][sbi + 1]);
                MMA16816(acc[mi][ni], ah, bl[pair][sbi], bl[pair][sbi + 1]);
                MMA16816(acc[mi][ni], al, bh[pair][sbi], bh[pair][sbi + 1]);
            }
        }
    }

    // ---- epilogue: scale by dis[row], store fp32 ----
    #pragma unroll
    for (int mi = 0; mi < 2; mi++) {
        int r0g = row0 + wm * 32 + mi * 16 + gp;
        int r1g = r0g + 8;
        float s0 = (r0g < M) ? dis[r0g] : 0.f;
        float s1 = (r1g < M) ? dis[r1g] : 0.f;
        #pragma unroll
        for (int ni = 0; ni < 4; ni++) {
            int c = wn * 32 + (ni >> 1) * 16 + (ni & 1) * 8 + tg * 2;
            if (r0g < M) {
                float2 o = make_float2(acc[mi][ni][0] * s0, acc[mi][ni][1] * s0);
                *(float2*)&H[(size_t)r0g * 128 + c] = o;
            }
            if (r1g < M) {
                float2 o = make_float2(acc[mi][ni][2] * s1, acc[mi][ni][3] * s1);
                *(float2*)&H[(size_t)r1g * 128 + c] = o;
            }
        }
    }
}

// ---------------------------------------------------------------------------
// Aggregation: warp per node, lane holds channels [lane*4, lane*4+4)
// SPLIT=true: relu + write bf16 hi/lo (consumed by next gemm)
// SPLIT=false: no relu, write fp32 (final output)
// ---------------------------------------------------------------------------
template <bool SPLIT>
__global__ __launch_bounds__(256) void aggregate_kernel(
    const float* __restrict__ h, const int* __restrict__ loc,
    const int* __restrict__ off, const int* __restrict__ col,
    const float* __restrict__ dis, const float* __restrict__ bias,
    float* __restrict__ outf, __nv_bfloat16* __restrict__ outh,
    __nv_bfloat16* __restrict__ outl, int n, int E)
{
    int w    = (blockIdx.x * blockDim.x + threadIdx.x) >> 5;
    int lane = threadIdx.x & 31;
    if (w >= n) return;

    int beg = loc[w] + off[w >> 10];
    int end = (w + 1 < n) ? (loc[w + 1] + off[(w + 1) >> 10]) : E;

    const float4* h4 = (const float4*)h;
    float4 acc = __ldg(&h4[w * 32 + lane]);   // self loop

    int j = beg;
    for (; j + 4 <= end; j += 4) {
        int s0 = __ldg(&col[j]);
        int s1 = __ldg(&col[j + 1]);
        int s2 = __ldg(&col[j + 2]);
        int s3 = __ldg(&col[j + 3]);
        float4 a0 = __ldg(&h4[s0 * 32 + lane]);
        float4 a1 = __ldg(&h4[s1 * 32 + lane]);
        float4 a2 = __ldg(&h4[s2 * 32 + lane]);
        float4 a3 = __ldg(&h4[s3 * 32 + lane]);
        acc.x += (a0.x + a1.x) + (a2.x + a3.x);
        acc.y += (a0.y + a1.y) + (a2.y + a3.y);
        acc.z += (a0.z + a1.z) + (a2.z + a3.z);
        acc.w += (a0.w + a1.w) + (a2.w + a3.w);
    }
    for (; j < end; j++) {
        int s = __ldg(&col[j]);
        float4 a = __ldg(&h4[s * 32 + lane]);
        acc.x += a.x; acc.y += a.y; acc.z += a.z; acc.w += a.w;
    }

    float dv = dis[w];
    float4 bv = ((const float4*)bias)[lane];
    acc.x = acc.x * dv + bv.x;
    acc.y = acc.y * dv + bv.y;
    acc.z = acc.z * dv + bv.z;
    acc.w = acc.w * dv + bv.w;
    if (SPLIT) {
        acc.x = fmaxf(acc.x, 0.f); acc.y = fmaxf(acc.y, 0.f);
        acc.z = fmaxf(acc.z, 0.f); acc.w = fmaxf(acc.w, 0.f);
        uint2 hv, lv;
        split4(acc, hv, lv);
        ((uint2*)outh)[w * 32 + lane] = hv;
        ((uint2*)outl)[w * 32 + lane] = lv;
    } else {
        ((float4*)outf)[w * 32 + lane] = acc;
    }
}

// ---------------------------------------------------------------------------
extern "C" void kernel_launch(void* const* d_in, const int* in_sizes, int n_in,
                              void* d_out, int out_size)
{
    const float* x      = (const float*)d_in[0];
    const float* W_role = (const float*)d_in[1];
    const float* b_role = (const float*)d_in[2];
    const float* W2     = (const float*)d_in[3];
    const float* b2     = (const float*)d_in[4];
    const float* W1     = (const float*)d_in[5];
    const float* b1     = (const float*)d_in[6];
    const int*   ei_nrm = (const int*)d_in[7];
    const int*   ei_rol = (const int*)d_in[8];

    const int n = in_sizes[0] / D;       // 50000
    const int E = in_sizes[7] / 2;       // 640000

    const int* src_n = ei_nrm;
    const int* dst_n = ei_nrm + E;
    const int* src_r = ei_rol;
    const int* dst_r = ei_rol + E;

    float *h_s, *dis_r, *dis_n;
    int *loc_r, *loc_n, *col_r, *col_n, *off_d;
    __nv_bfloat16 *wth, *wtl, *xh, *xl, *ah, *al;
    cudaGetSymbolAddress((void**)&h_s,   g_h);
    cudaGetSymbolAddress((void**)&dis_r, g_dis_role);
    cudaGetSymbolAddress((void**)&dis_n, g_dis_norm);
    cudaGetSymbolAddress((void**)&loc_r, g_loc_role);
    cudaGetSymbolAddress((void**)&loc_n, g_loc_norm);
    cudaGetSymbolAddress((void**)&col_r, g_col_role);
    cudaGetSymbolAddress((void**)&col_n, g_col_norm);
    cudaGetSymbolAddress((void**)&off_d, g_off);
    cudaGetSymbolAddress((void**)&wth,   g_WTh);
    cudaGetSymbolAddress((void**)&wtl,   g_WTl);
    cudaGetSymbolAddress((void**)&xh,    g_xh);
    cudaGetSymbolAddress((void**)&xl,    g_xl);
    cudaGetSymbolAddress((void**)&ah,    g_ah);
    cudaGetSymbolAddress((void**)&al,    g_al);

    cudaFuncSetAttribute(gemm_tc_kernel,
                         cudaFuncAttributeMaxDynamicSharedMemorySize,
                         SMEM_TOTAL_GEMM);

    const int TB  = 256;
    const int nbN = (n + TB - 1) / TB;
    const int NS4 = n * 32;              // float4 count of x
    const int nbS = (NS4 + TB - 1) / TB; // covers E too (E < NS4)
    const int nbE = (E + TB - 1) / TB;
    const int nch = (n + 1023) >> 10;

    const int gemmBlocks = (n + 63) / 64;
    const int aggBlocks  = (n + 7) / 8;

    // launch idx:
    prep_kernel<<<nbN, TB>>>(W_role, W2, W1, n);                         // 0
    count_split_kernel<<<nbS, TB>>>(dst_n, dst_r, E,
                                    (const float4*)x, NS4);              // 1
    scan_local_kernel<<<dim3(nch, 2), 1024>>>(n);                        // 2
    // gemm1 needs xh/xl + dis_r -> launch idx 3 (ncu target)
    gemm_tc_kernel<<<gemmBlocks, 256, SMEM_TOTAL_GEMM>>>(xh, xl, wth, wtl,
                                                         dis_r, h_s, n); // 3
    scan_mid_kernel<<<1, 64>>>(nch);                                     // 4
    scatter_kernel<<<dim3(nbE, 2), TB>>>(src_n, dst_n, src_r, dst_r, E); // 5

    // ---- layer 1 aggregate (role graph): relu + split ----
    aggregate_kernel<true><<<aggBlocks, 256>>>(h_s, loc_r, off_d + NCH_MAX,
                                               col_r, dis_r, b_role,
                                               nullptr, ah, al, n, E);
    // ---- layer 2: normal graph ----
    gemm_tc_kernel<<<gemmBlocks, 256, SMEM_TOTAL_GEMM>>>(ah, al,
                                                         wth + D * D,
                                                         wtl + D * D,
                                                         dis_n, h_s, n);
    aggregate_kernel<true><<<aggBlocks, 256>>>(h_s, loc_n, off_d,
                                               col_n, dis_n, b2,
                                               nullptr, ah, al, n, E);
    // ---- layer 3: normal graph, fp32 out ----
    gemm_tc_kernel<<<gemmBlocks, 256, SMEM_TOTAL_GEMM>>>(ah, al,
                                                         wth + 2 * D * D,
                                                         wtl + 2 * D * D,
                                                         dis_n, h_s, n);
    aggregate_kernel<false><<<aggBlocks, 256>>>(h_s, loc_n, off_d,
                                                col_n, dis_n, b1,
                                                (float*)d_out, nullptr, nullptr,
                                                n, E);
}

// round 12
// speedup vs baseline: 1.1319x; 1.1319x over previous
#include <cuda_runtime.h>
#include <cuda_bf16.h>
#include <cstdint>
#include <stdint.h>

// ---------------------------------------------------------------------------
// 3-layer GCN:  relu(gcn(x,Wr)) -> relu(gcn(.,W2)) -> gcn(.,W1)
// gcn(x,W): out[v] = dis[v]*( sum_{s->v} h_s[s] + h_s[v] ) + b
//           where h_s = (x@W) * dis[row],  dis = rsqrt(indeg+1)
// GEMM: persistent CTAs, B (weights, bf16 hi/lo) resident in smem, A (fp32)
// streamed via register-staged double buffer with on-the-fly bf16 split.
// acc += Ah*Bh + Ah*Bl + Al*Bh  (~fp32 accuracy on tensor cores).
// ---------------------------------------------------------------------------

#define N_MAX 50000
#define E_MAX 640000
#define D     128
#define NCH_MAX 64

// scratch (static device memory: allocation-free rule)
__device__ float g_h[N_MAX * D];        // h_scaled
__device__ float g_a[N_MAX * D];        // layer activation
__device__ float g_dis_role[N_MAX];
__device__ float g_dis_norm[N_MAX];
__device__ int   g_cnt_role[N_MAX];
__device__ int   g_cnt_norm[N_MAX];
__device__ int   g_fill_role[N_MAX];
__device__ int   g_fill_norm[N_MAX];
__device__ int   g_loc_role[N_MAX];
__device__ int   g_loc_norm[N_MAX];
__device__ int   g_tot[2 * NCH_MAX];
__device__ int   g_off[2 * NCH_MAX];
__device__ int   g_col_role[E_MAX];
__device__ int   g_col_norm[E_MAX];
// split+transposed weights: [w][n][k] bf16 hi / lo
__device__ __align__(16) __nv_bfloat16 g_WTh[3 * D * D];
__device__ __align__(16) __nv_bfloat16 g_WTl[3 * D * D];

// ---------------------------------------------------------------------------
__global__ void prep_kernel(const float* __restrict__ Wr,
                            const float* __restrict__ W2,
                            const float* __restrict__ W1, int n) {
    int i = blockIdx.x * blockDim.x + threadIdx.x;
    if (i < n) {
        g_cnt_role[i]  = 0;
        g_cnt_norm[i]  = 0;
        g_fill_role[i] = 0;
        g_fill_norm[i] = 0;
    }
    if (i < 3 * D * D) {
        int w = i >> 14, rem = i & 16383;
        int k = rem >> 7, nn = rem & 127;
        const float* W = (w == 0) ? Wr : (w == 1) ? W2 : W1;
        float v = W[k * D + nn];
        __nv_bfloat16 h = __float2bfloat16(v);
        __nv_bfloat16 l = __float2bfloat16(v - __bfloat162float(h));
        g_WTh[w * D * D + nn * D + k] = h;   // [n][k] layout (col-major B)
        g_WTl[w * D * D + nn * D + k] = l;
    }
}

__global__ void count_kernel(const int* __restrict__ dst_n,
                             const int* __restrict__ dst_r, int E) {
    int e = blockIdx.x * blockDim.x + threadIdx.x;
    if (e < E) {
        atomicAdd(&g_cnt_norm[dst_n[e]], 1);
        atomicAdd(&g_cnt_role[dst_r[e]], 1);
    }
}

__global__ __launch_bounds__(1024) void scan_local_kernel(int n) {
    const int g = blockIdx.y;
    const int* __restrict__ cnt = g ? g_cnt_role : g_cnt_norm;
    int* __restrict__ loc       = g ? g_loc_role : g_loc_norm;
    float* __restrict__ dis     = g ? g_dis_role : g_dis_norm;

    __shared__ int wsum[32];
    int tid  = threadIdx.x;
    int lane = tid & 31, wid = tid >> 5;
    int i = (blockIdx.x << 10) + tid;
    int v = (i < n) ? cnt[i] : 0;

    int s = v;
    #pragma unroll
    for (int o = 1; o < 32; o <<= 1) {
        int t = __shfl_up_sync(0xffffffffu, s, o);
        if (lane >= o) s += t;
    }
    if (lane == 31) wsum[wid] = s;
    __syncthreads();
    if (wid == 0) {
        int w = wsum[lane];
        #pragma unroll
        for (int o = 1; o < 32; o <<= 1) {
            int t = __shfl_up_sync(0xffffffffu, w, o);
            if (lane >= o) w += t;
        }
        wsum[lane] = w;
    }
    __syncthreads();
    int woff = (wid == 0) ? 0 : wsum[wid - 1];
    int ex = s - v + woff;
    if (i < n) {
        loc[i] = ex;
        dis[i] = rsqrtf((float)(v + 1));
    }
    if (tid == 0) g_tot[g * NCH_MAX + blockIdx.x] = wsum[31];
}

__global__ void scan_mid_kernel(int nch) {
    int g = threadIdx.x >> 5, lane = threadIdx.x & 31;
    int carry = 0;
    for (int c0 = 0; c0 < nch; c0 += 32) {
        int idx = c0 + lane;
        int v = (idx < nch) ? g_tot[g * NCH_MAX + idx] : 0;
        int s = v;
        #pragma unroll
        for (int o = 1; o < 32; o <<= 1) {
            int t = __shfl_up_sync(0xffffffffu, s, o);
            if (lane >= o) s += t;
        }
        if (idx < nch) g_off[g * NCH_MAX + idx] = carry + s - v;
        carry += __shfl_sync(0xffffffffu, s, 31);
    }
}

__global__ void scatter_kernel(const int* __restrict__ src_n,
                               const int* __restrict__ dst_n,
                               const int* __restrict__ src_r,
                               const int* __restrict__ dst_r, int E) {
    const int g = blockIdx.y;
    const int* __restrict__ src = g ? src_r : src_n;
    const int* __restrict__ dst = g ? dst_r : dst_n;
    const int* __restrict__ loc = g ? g_loc_role : g_loc_norm;
    int* __restrict__ fill      = g ? g_fill_role : g_fill_norm;
    int* __restrict__ col       = g ? g_col_role : g_col_norm;
    const int* off = &g_off[g * NCH_MAX];

    int e = blockIdx.x * blockDim.x + threadIdx.x;
    if (e < E) {
        int d = dst[e];
        int pos = loc[d] + off[d >> 10] + atomicAdd(&fill[d], 1);
        col[pos] = src[e];
    }
}

// ---------------------------------------------------------------------------
// Persistent tensor-core GEMM: H = (X @ W) * dis[row].
// B resident in smem (hi 0..34815, lo 34816..69631, rows 272B padded).
// A double-buffered: 2 stages of 64x32 (hi 5120 + lo 5120), reg-staged LDG
// with fp32->bf16 hi/lo split at STS time. ONE __syncthreads per stage.
// 256 threads = 8 warps (2x4), warp tile 32x32.
// ---------------------------------------------------------------------------
#define BROW 272u
#define SM_BH 0u
#define SM_BL 34816u
#define SM_A  69632u
#define A_STAGE 10240u
#define SMEM_TOTAL_GEMM 90112u     // 88 KB -> 2 CTAs/SM

#define MMA16816(d, a, b0, b1)                                                \
    asm volatile(                                                             \
        "mma.sync.aligned.m16n8k16.row.col.f32.bf16.bf16.f32 "                \
        "{%0,%1,%2,%3}, {%4,%5,%6,%7}, {%8,%9}, {%0,%1,%2,%3};"               \
        : "+f"((d)[0]), "+f"((d)[1]), "+f"((d)[2]), "+f"((d)[3])              \
        : "r"((a)[0]), "r"((a)[1]), "r"((a)[2]), "r"((a)[3]),                 \
          "r"(b0), "r"(b1))

#define LDSM4(r, addr)                                                        \
    asm volatile(                                                             \
        "ldmatrix.sync.aligned.m8n8.x4.shared.b16 {%0,%1,%2,%3}, [%4];"       \
        : "=r"((r)[0]), "=r"((r)[1]), "=r"((r)[2]), "=r"((r)[3])              \
        : "r"(addr))

__device__ __forceinline__ void cp16(uint32_t dst, const void* src) {
    asm volatile("cp.async.cg.shared.global [%0], [%1], 16;"
                 :: "r"(dst), "l"(src));
}

__global__ __launch_bounds__(256, 2) void gemm_tc_kernel(
    const float* __restrict__ X,
    const __nv_bfloat16* __restrict__ WTh,
    const __nv_bfloat16* __restrict__ WTl,
    const float* __restrict__ dis, float* __restrict__ H, int M, int nt)
{
    extern __shared__ char sm[];
    const uint32_t sb = (uint32_t)__cvta_generic_to_shared(sm);

    const int t    = threadIdx.x;
    const int lane = t & 31, wid = t >> 5;
    const int wm = wid >> 2;          // 0..1 : rows wm*32
    const int wn = wid & 3;           // 0..3 : cols wn*32
    const int gp = lane >> 2;
    const int tg = lane & 3;
    const int G  = gridDim.x;

    if (blockIdx.x >= nt) return;

    // ldmatrix lane address components
    const int laneRowA = (lane & 7) + ((lane >> 3) & 1) * 8;
    const int laneKA   = (lane >> 4) * 16;                 // bytes
    const int laneRowB = (lane & 7) + ((lane >> 4) & 1) * 8;
    const int laneKB   = ((lane >> 3) & 1) * 16;           // bytes

    const float4* X4 = (const float4*)X;

    // ---- one-shot resident B load (hi+lo), 8 x 16B chunks per thread each
    {
        #pragma unroll
        for (int j = 0; j < 8; j++) {
            int c = j * 256 + t;                  // 0..2047
            int row = c >> 4, ch = c & 15;
            uint32_t doff = (uint32_t)row * BROW + (uint32_t)ch * 16;
            size_t   soff = (size_t)row * 128 + ch * 8;
            cp16(sb + SM_BH + doff, WTh + soff);
            cp16(sb + SM_BL + doff, WTl + soff);
        }
        asm volatile("cp.async.commit_group;");
    }

    // A staging state
    const int ar0 = t >> 3, ac4 = t & 7;          // rows ar0, ar0+32
    float4 aReg[2];

    auto loadA = [&](int row0, int k0) {
        #pragma unroll
        for (int i = 0; i < 2; i++) {
            int r = row0 + ar0 + i * 32;
            aReg[i] = (r < M) ? X4[(size_t)r * 32 + (k0 >> 2) + ac4]
                              : make_float4(0.f, 0.f, 0.f, 0.f);
        }
    };
    auto stsA = [&](int s) {
        char* base = sm + SM_A + (uint32_t)s * A_STAGE;
        #pragma unroll
        for (int i = 0; i < 2; i++) {
            int r = ar0 + i * 32;
            float4 v = aReg[i];
            __nv_bfloat16 hx = __float2bfloat16(v.x);
            __nv_bfloat16 hy = __float2bfloat16(v.y);
            __nv_bfloat16 hz = __float2bfloat16(v.z);
            __nv_bfloat16 hw = __float2bfloat16(v.w);
            __nv_bfloat16 lx = __float2bfloat16(v.x - __bfloat162float(hx));
            __nv_bfloat16 ly = __float2bfloat16(v.y - __bfloat162float(hy));
            __nv_bfloat16 lz = __float2bfloat16(v.z - __bfloat162float(hz));
            __nv_bfloat16 lw = __float2bfloat16(v.w - __bfloat162float(hw));
            uint2 hv, lv;
            hv.x = (uint32_t)__bfloat16_as_ushort(hx) |
                   ((uint32_t)__bfloat16_as_ushort(hy) << 16);
            hv.y = (uint32_t)__bfloat16_as_ushort(hz) |
                   ((uint32_t)__bfloat16_as_ushort(hw) << 16);
            lv.x = (uint32_t)__bfloat16_as_ushort(lx) |
                   ((uint32_t)__bfloat16_as_ushort(ly) << 16);
            lv.y = (uint32_t)__bfloat16_as_ushort(lz) |
                   ((uint32_t)__bfloat16_as_ushort(lw) << 16);
            *(uint2*)(base + r * 80 + ac4 * 8)         = hv;
            *(uint2*)(base + 5120 + r * 80 + ac4 * 8)  = lv;
        }
    };

    float acc[2][4][4];
    #pragma unroll
    for (int mi = 0; mi < 2; mi++)
        #pragma unroll
        for (int ni = 0; ni < 4; ni++)
            #pragma unroll
            for (int j = 0; j < 4; j++) acc[mi][ni][j] = 0.f;

    // ---- prologue: A(first tile, k0=0) into stage 0; wait B ----
    loadA(blockIdx.x * 64, 0);
    asm volatile("cp.async.wait_group 0;");
    stsA(0);
    __syncthreads();

    int s = 0;
    for (int tile = blockIdx.x; tile < nt; tile += G) {
        const int row0 = tile * 64;
        #pragma unroll
        for (int k0i = 0; k0i < 4; k0i++) {
            // prefetch regs for next stage
            int pt = tile, pk = k0i + 1;
            if (pk == 4) { pk = 0; pt = (tile + G < nt) ? tile + G : -1; }
            if (pt >= 0) loadA(pt * 64, pk * 32);

            // compute current stage
            const uint32_t aHb = sb + SM_A + (uint32_t)s * A_STAGE;
            const uint32_t aLb = aHb + 5120u;
            #pragma unroll
            for (int kkl = 0; kkl < 32; kkl += 16) {
                const int kg = k0i * 32 + kkl;
                uint32_t bh[2][4], bl[2][4];
                #pragma unroll
                for (int pair = 0; pair < 2; pair++) {
                    uint32_t off = (uint32_t)(wn * 32 + pair * 16 + laneRowB) * BROW
                                   + (uint32_t)(kg * 2 + laneKB);
                    LDSM4(bh[pair], sb + SM_BH + off);
                    LDSM4(bl[pair], sb + SM_BL + off);
                }
                #pragma unroll
                for (int mi = 0; mi < 2; mi++) {
                    uint32_t ah[4], al[4];
                    uint32_t off = (uint32_t)((wm * 32 + mi * 16 + laneRowA) * 80
                                              + kkl * 2 + laneKA);
                    LDSM4(ah, aHb + off);
                    LDSM4(al, aLb + off);
                    #pragma unroll
                    for (int ni = 0; ni < 4; ni++) {
                        int pair = ni >> 1, sbi = (ni & 1) * 2;
                        MMA16816(acc[mi][ni], ah, bh[pair][sbi], bh[pair][sbi + 1]);
                        MMA16816(acc[mi][ni], ah, bl[pair][sbi], bl[pair][sbi + 1]);
                        MMA16816(acc[mi][ni], al, bh[pair][sbi], bh[pair][sbi + 1]);
                    }
                }
            }

            // epilogue on last k-step of the tile (overlaps prefetch LDGs)
            if (k0i == 3) {
                #pragma unroll
                for (int mi = 0; mi < 2; mi++) {
                    int r0g = row0 + wm * 32 + mi * 16 + gp;
                    int r1g = r0g + 8;
                    float s0 = (r0g < M) ? dis[r0g] : 0.f;
                    float s1 = (r1g < M) ? dis[r1g] : 0.f;
                    #pragma unroll
                    for (int ni = 0; ni < 4; ni++) {
                        int c = wn * 32 + (ni >> 1) * 16 + (ni & 1) * 8 + tg * 2;
                        if (r0g < M) {
                            float2 o = make_float2(acc[mi][ni][0] * s0,
                                                   acc[mi][ni][1] * s0);
                            *(float2*)&H[(size_t)r0g * 128 + c] = o;
                        }
                        if (r1g < M) {
                            float2 o = make_float2(acc[mi][ni][2] * s1,
                                                   acc[mi][ni][3] * s1);
                            *(float2*)&H[(size_t)r1g * 128 + c] = o;
                        }
                        acc[mi][ni][0] = 0.f; acc[mi][ni][1] = 0.f;
                        acc[mi][ni][2] = 0.f; acc[mi][ni][3] = 0.f;
                    }
                }
            }

            if (pt >= 0) stsA(s ^ 1);
            __syncthreads();
            s ^= 1;
        }
    }
}

// ---------------------------------------------------------------------------
// Aggregation: warp per node, lane holds channels [lane*4, lane*4+4)
// ---------------------------------------------------------------------------
template <bool RELU>
__global__ __launch_bounds__(256) void aggregate_kernel(
    const float* __restrict__ h, const int* __restrict__ loc,
    const int* __restrict__ off, const int* __restrict__ col,
    const float* __restrict__ dis, const float* __restrict__ bias,
    float* __restrict__ out, int n, int E)
{
    int w    = (blockIdx.x * blockDim.x + threadIdx.x) >> 5;
    int lane = threadIdx.x & 31;
    if (w >= n) return;

    int beg = loc[w] + off[w >> 10];
    int end = (w + 1 < n) ? (loc[w + 1] + off[(w + 1) >> 10]) : E;

    const float4* h4 = (const float4*)h;
    float4 acc = __ldg(&h4[w * 32 + lane]);   // self loop

    int j = beg;
    for (; j + 4 <= end; j += 4) {
        int s0 = __ldg(&col[j]);
        int s1 = __ldg(&col[j + 1]);
        int s2 = __ldg(&col[j + 2]);
        int s3 = __ldg(&col[j + 3]);
        float4 a0 = __ldg(&h4[s0 * 32 + lane]);
        float4 a1 = __ldg(&h4[s1 * 32 + lane]);
        float4 a2 = __ldg(&h4[s2 * 32 + lane]);
        float4 a3 = __ldg(&h4[s3 * 32 + lane]);
        acc.x += (a0.x + a1.x) + (a2.x + a3.x);
        acc.y += (a0.y + a1.y) + (a2.y + a3.y);
        acc.z += (a0.z + a1.z) + (a2.z + a3.z);
        acc.w += (a0.w + a1.w) + (a2.w + a3.w);
    }
    for (; j < end; j++) {
        int s = __ldg(&col[j]);
        float4 a = __ldg(&h4[s * 32 + lane]);
        acc.x += a.x; acc.y += a.y; acc.z += a.z; acc.w += a.w;
    }

    float dv = dis[w];
    float4 bv = ((const float4*)bias)[lane];
    acc.x = acc.x * dv + bv.x;
    acc.y = acc.y * dv + bv.y;
    acc.z = acc.z * dv + bv.z;
    acc.w = acc.w * dv + bv.w;
    if (RELU) {
        acc.x = fmaxf(acc.x, 0.f); acc.y = fmaxf(acc.y, 0.f);
        acc.z = fmaxf(acc.z, 0.f); acc.w = fmaxf(acc.w, 0.f);
    }
    ((float4*)out)[w * 32 + lane] = acc;
}

// ---------------------------------------------------------------------------
extern "C" void kernel_launch(void* const* d_in, const int* in_sizes, int n_in,
                              void* d_out, int out_size)
{
    const float* x      = (const float*)d_in[0];
    const float* W_role = (const float*)d_in[1];
    const float* b_role = (const float*)d_in[2];
    const float* W2     = (const float*)d_in[3];
    const float* b2     = (const float*)d_in[4];
    const float* W1     = (const float*)d_in[5];
    const float* b1     = (const float*)d_in[6];
    const int*   ei_nrm = (const int*)d_in[7];
    const int*   ei_rol = (const int*)d_in[8];

    const int n = in_sizes[0] / D;       // 50000
    const int E = in_sizes[7] / 2;       // 640000

    const int* src_n = ei_nrm;
    const int* dst_n = ei_nrm + E;
    const int* src_r = ei_rol;
    const int* dst_r = ei_rol + E;

    float *h_s, *act, *dis_r, *dis_n;
    int *loc_r, *loc_n, *col_r, *col_n, *off_d;
    __nv_bfloat16 *wth, *wtl;
    cudaGetSymbolAddress((void**)&h_s,   g_h);
    cudaGetSymbolAddress((void**)&act,   g_a);
    cudaGetSymbolAddress((void**)&dis_r, g_dis_role);
    cudaGetSymbolAddress((void**)&dis_n, g_dis_norm);
    cudaGetSymbolAddress((void**)&loc_r, g_loc_role);
    cudaGetSymbolAddress((void**)&loc_n, g_loc_norm);
    cudaGetSymbolAddress((void**)&col_r, g_col_role);
    cudaGetSymbolAddress((void**)&col_n, g_col_norm);
    cudaGetSymbolAddress((void**)&off_d, g_off);
    cudaGetSymbolAddress((void**)&wth,   g_WTh);
    cudaGetSymbolAddress((void**)&wtl,   g_WTl);

    cudaFuncSetAttribute(gemm_tc_kernel,
                         cudaFuncAttributeMaxDynamicSharedMemorySize,
                         SMEM_TOTAL_GEMM);

    const int TB  = 256;
    const int nbN = (n + TB - 1) / TB;
    const int nbE = (E + TB - 1) / TB;
    const int nch = (n + 1023) >> 10;

    const int nt = (n + 63) / 64;        // 782 tiles
    int gemmGrid = 296;                  // 2 persistent CTAs x 148 SMs
    if (gemmGrid > nt) gemmGrid = nt;
    const int aggBlocks = (n + 7) / 8;

    // launch idx:
    prep_kernel<<<nbN, TB>>>(W_role, W2, W1, n);                         // 0
    count_kernel<<<nbE, TB>>>(dst_n, dst_r, E);                          // 1
    scan_local_kernel<<<dim3(nch, 2), 1024>>>(n);                        // 2
    // gemm1 needs only dis_r + split weights -> launch idx 3 (ncu target)
    gemm_tc_kernel<<<gemmGrid, 256, SMEM_TOTAL_GEMM>>>(x, wth, wtl,
                                                       dis_r, h_s, n, nt); // 3
    scan_mid_kernel<<<1, 64>>>(nch);                                     // 4
    scatter_kernel<<<dim3(nbE, 2), TB>>>(src_n, dst_n, src_r, dst_r, E); // 5

    // ---- layer 1 aggregate (role graph), relu ----
    aggregate_kernel<true><<<aggBlocks, 256>>>(h_s, loc_r, off_d + NCH_MAX,
                                               col_r, dis_r, b_role, act, n, E);
    // ---- layer 2: normal graph ----
    gemm_tc_kernel<<<gemmGrid, 256, SMEM_TOTAL_GEMM>>>(act, wth + D * D,
                                                       wtl + D * D,
                                                       dis_n, h_s, n, nt);
    aggregate_kernel<true><<<aggBlocks, 256>>>(h_s, loc_n, off_d,
                                               col_n, dis_n, b2, act, n, E);
    // ---- layer 3: normal graph, no relu, write d_out ----
    gemm_tc_kernel<<<gemmGrid, 256, SMEM_TOTAL_GEMM>>>(act, wth + 2 * D * D,
                                                       wtl + 2 * D * D,
                                                       dis_n, h_s, n, nt);
    aggregate_kernel<false><<<aggBlocks, 256>>>(h_s, loc_n, off_d,
                                                col_n, dis_n, b1,
                                                (float*)d_out, n, E);
}